// round 12
// baseline (speedup 1.0000x reference)
#include <cuda_runtime.h>
#include <math.h>

#define NNODES 50000
#define NFEAT  512
#define NHID   256
#define NCLASS 40

// Scratch (no cudaMalloc allowed): ping-pong activation buffers + CSR row ptr.
__device__ float g_buf1[NNODES * NHID];
__device__ float g_buf2[NNODES * NHID];
__device__ int   g_rowptr[NNODES + 1];

// ---------------------------------------------------------------------------
// Build CSR row pointers from sorted edge_rows via per-row lower_bound.
// ---------------------------------------------------------------------------
__global__ void rowptr_kernel(const int* __restrict__ rows, int E) {
    int r = blockIdx.x * blockDim.x + threadIdx.x;
    if (r > NNODES) return;
    int lo = 0, hi = E;
    while (lo < hi) {
        int mid = (lo + hi) >> 1;
        if (rows[mid] < r) lo = mid + 1; else hi = mid;
    }
    g_rowptr[r] = lo;
}

// ---------------------------------------------------------------------------
// SGEMM + bias: C[M, 256] = A[M, K] @ B[K, 256] + bias
// 128x128 tile, BK=8, 256 threads, 8x8 per-thread microtile in SPLIT-TILE
// layout (conflict-free smem). Accumulators packed as f32x2 pairs; inner
// product uses PTX fma.rn.f32x2 (sm_103a dual-fp32 path, 32 FFMA2 vs 64 FFMA
// per k-step). Double-buffered smem pipeline; unroll capped at 2.
// ---------------------------------------------------------------------------
template <int K>
__global__ __launch_bounds__(256)
void sgemm_bias_kernel(const float* __restrict__ A,
                       const float* __restrict__ B,
                       const float* __restrict__ bias,
                       float* __restrict__ C, int M) {
    __shared__ float As[2][8][128];   // transposed A tile: As[s][k][m]
    __shared__ float Bs[2][8][128];   // Bs[s][k][n]

    const int tid = threadIdx.x;
    const int tx = tid % 16;
    const int ty = tid / 16;
    const int rowBase = blockIdx.y * 128;
    const int colBase = blockIdx.x * 128;

    // A load mapping: each thread one float4; row = tid/2, kcol4 = (tid%2)*4
    const int aRow = tid >> 1;
    const int aK4  = (tid & 1) * 4;
    // B load mapping: row = tid/32 (0..7), col4 = (tid%32)*4
    const int bRow = tid >> 5;
    const int bC4  = (tid & 31) * 4;

    // acc2[i][j2] = packed pair (C[i][2*j2], C[i][2*j2+1]) within this
    // thread's 8x8 microtile (split-tile column/row mapping).
    unsigned long long acc2[8][4];
#pragma unroll
    for (int i = 0; i < 8; i++)
#pragma unroll
        for (int j = 0; j < 4; j++) acc2[i][j] = 0ULL;

    const int gARow = rowBase + aRow;
    const bool aValid = (gARow < M);

    // ---- prologue: load k-slice 0 into stage 0 ----
    {
        float4 av = make_float4(0.f, 0.f, 0.f, 0.f);
        if (aValid)
            av = *reinterpret_cast<const float4*>(&A[(long)gARow * K + aK4]);
        As[0][aK4 + 0][aRow] = av.x;
        As[0][aK4 + 1][aRow] = av.y;
        As[0][aK4 + 2][aRow] = av.z;
        As[0][aK4 + 3][aRow] = av.w;
        float4 bv = *reinterpret_cast<const float4*>(&B[(long)bRow * NHID + colBase + bC4]);
        *reinterpret_cast<float4*>(&Bs[0][bRow][bC4]) = bv;
    }
    __syncthreads();

#pragma unroll 2
    for (int kb = 0; kb < K; kb += 8) {
        const int cur = (kb >> 3) & 1;
        const bool hasNext = (kb + 8 < K);

        // prefetch next k-slice into registers (overlaps with compute below)
        float4 av = make_float4(0.f, 0.f, 0.f, 0.f);
        float4 bv = make_float4(0.f, 0.f, 0.f, 0.f);
        if (hasNext) {
            if (aValid)
                av = *reinterpret_cast<const float4*>(&A[(long)gARow * K + kb + 8 + aK4]);
            bv = *reinterpret_cast<const float4*>(&B[(long)(kb + 8 + bRow) * NHID + colBase + bC4]);
        }

        // compute on current stage (split-tile operand fetch: halves 16B apart)
#pragma unroll
        for (int k = 0; k < 8; k++) {
            float a[8], b[8];
            *reinterpret_cast<float4*>(&a[0]) = *reinterpret_cast<const float4*>(&As[cur][k][ty * 4]);
            *reinterpret_cast<float4*>(&a[4]) = *reinterpret_cast<const float4*>(&As[cur][k][64 + ty * 4]);
            *reinterpret_cast<float4*>(&b[0]) = *reinterpret_cast<const float4*>(&Bs[cur][k][tx * 4]);
            *reinterpret_cast<float4*>(&b[4]) = *reinterpret_cast<const float4*>(&Bs[cur][k][64 + tx * 4]);

            unsigned long long b2[4];
#pragma unroll
            for (int j = 0; j < 4; j++)
                asm("mov.b64 %0, {%1, %2};" : "=l"(b2[j]) : "f"(b[2 * j]), "f"(b[2 * j + 1]));

#pragma unroll
            for (int i = 0; i < 8; i++) {
                unsigned long long a2;
                asm("mov.b64 %0, {%1, %1};" : "=l"(a2) : "f"(a[i]));
#pragma unroll
                for (int j = 0; j < 4; j++)
                    asm("fma.rn.f32x2 %0, %1, %2, %0;" : "+l"(acc2[i][j]) : "l"(a2), "l"(b2[j]));
            }
        }

        // store prefetched slice into the other stage
        if (hasNext) {
            const int nxt = cur ^ 1;
            As[nxt][aK4 + 0][aRow] = av.x;
            As[nxt][aK4 + 1][aRow] = av.y;
            As[nxt][aK4 + 2][aRow] = av.z;
            As[nxt][aK4 + 3][aRow] = av.w;
            *reinterpret_cast<float4*>(&Bs[nxt][bRow][bC4]) = bv;
            __syncthreads();
        }
    }

    // Epilogue: unpack, add bias, store both column halves (bounds-checked).
    float bcol[8];
#pragma unroll
    for (int j = 0; j < 4; j++) bcol[j] = bias[colBase + tx * 4 + j];
#pragma unroll
    for (int j = 4; j < 8; j++) bcol[j] = bias[colBase + 64 + tx * 4 + (j - 4)];

#pragma unroll
    for (int i = 0; i < 8; i++) {
        const int row = rowBase + (i < 4 ? ty * 4 + i : 64 + ty * 4 + (i - 4));
        if (row < M) {
            float c[8];
#pragma unroll
            for (int j = 0; j < 4; j++)
                asm("mov.b64 {%0, %1}, %2;" : "=f"(c[2 * j]), "=f"(c[2 * j + 1]) : "l"(acc2[i][j]));
            float4 v0 = make_float4(c[0] + bcol[0], c[1] + bcol[1],
                                    c[2] + bcol[2], c[3] + bcol[3]);
            float4 v1 = make_float4(c[4] + bcol[4], c[5] + bcol[5],
                                    c[6] + bcol[6], c[7] + bcol[7]);
            *reinterpret_cast<float4*>(&C[(long)row * NHID + colBase + tx * 4]) = v0;
            *reinterpret_cast<float4*>(&C[(long)row * NHID + colBase + 64 + tx * 4]) = v1;
        }
    }
}

// ---------------------------------------------------------------------------
// SpMM + ReLU: out[r, :] = relu( sum_e vals[e] * H[cols[e], :] ) over CSR row r.
// WARP-PER-ROW: 8 warps/block, one row each. Lane l owns features [8l, 8l+8)
// as two float4s (2 indep LDG.128 per edge -> MLP=2, 8 FMA chains). Edge
// (col,val) pairs distributed one-per-lane and broadcast via shfl — no smem,
// no __syncthreads (warp-uniform trip counts make full-mask shfl safe).
// ---------------------------------------------------------------------------
__global__ __launch_bounds__(256)
void spmm_relu_kernel(const int* __restrict__ cols,
                      const float* __restrict__ vals,
                      const float* __restrict__ H,
                      float* __restrict__ out) {
    const int warp = threadIdx.x >> 5;
    const int lane = threadIdx.x & 31;
    const int r = blockIdx.x * 8 + warp;
    if (r >= NNODES) return;

    const int start = g_rowptr[r];
    const int end   = g_rowptr[r + 1];
    const int fbase = lane * 8;

    float4 acc0 = make_float4(0.f, 0.f, 0.f, 0.f);
    float4 acc1 = make_float4(0.f, 0.f, 0.f, 0.f);

    for (int base = start; base < end; base += 32) {
        int  c = 0;
        float v = 0.f;
        const int e = base + lane;
        if (e < end) { c = cols[e]; v = vals[e]; }
        const int n = min(32, end - base);

        for (int j = 0; j < n; j++) {
            const int   cj = __shfl_sync(0xffffffffu, c, j);
            const float vj = __shfl_sync(0xffffffffu, v, j);
            const float4* hp = reinterpret_cast<const float4*>(&H[(long)cj * NHID + fbase]);
            const float4 h0 = hp[0];
            const float4 h1 = hp[1];
            acc0.x = fmaf(vj, h0.x, acc0.x);
            acc0.y = fmaf(vj, h0.y, acc0.y);
            acc0.z = fmaf(vj, h0.z, acc0.z);
            acc0.w = fmaf(vj, h0.w, acc0.w);
            acc1.x = fmaf(vj, h1.x, acc1.x);
            acc1.y = fmaf(vj, h1.y, acc1.y);
            acc1.z = fmaf(vj, h1.z, acc1.z);
            acc1.w = fmaf(vj, h1.w, acc1.w);
        }
    }

    float4* op = reinterpret_cast<float4*>(&out[(long)r * NHID + fbase]);
    op[0] = make_float4(fmaxf(acc0.x, 0.f), fmaxf(acc0.y, 0.f),
                        fmaxf(acc0.z, 0.f), fmaxf(acc0.w, 0.f));
    op[1] = make_float4(fmaxf(acc1.x, 0.f), fmaxf(acc1.y, 0.f),
                        fmaxf(acc1.z, 0.f), fmaxf(acc1.w, 0.f));
}

// ---------------------------------------------------------------------------
// Fused FC + log_softmax: out[r, c] = log_softmax(Z[r,:] @ Wfc + bfc)[c]
// 256 threads; 6 rows/block x 40 classes (threads 240..255 idle).
// ---------------------------------------------------------------------------
__global__ __launch_bounds__(256)
void fc_logsoftmax_kernel(const float* __restrict__ Z,
                          const float* __restrict__ Wfc,
                          const float* __restrict__ bfc,
                          float* __restrict__ out, int M) {
    const int ROWS = 6;
    __shared__ float zs[ROWS][NHID];
    __shared__ float lg[ROWS][NCLASS];
    __shared__ float red[ROWS][2];

    const int tid = threadIdx.x;
    const int rowBase = blockIdx.x * ROWS;

    for (int i = tid; i < ROWS * NHID; i += blockDim.x) {
        int lr = i / NHID, k = i % NHID;
        int gr = rowBase + lr;
        zs[lr][k] = (gr < M) ? Z[(long)gr * NHID + k] : 0.f;
    }
    __syncthreads();

    const int lr = tid / NCLASS;
    const int c  = tid % NCLASS;

    if (lr < ROWS) {
        float acc = bfc[c];
#pragma unroll 4
        for (int k = 0; k < NHID; k++)
            acc = fmaf(zs[lr][k], Wfc[k * NCLASS + c], acc);
        lg[lr][c] = acc;
    }
    __syncthreads();

    if (lr < ROWS && c == 0) {
        float m = -INFINITY;
        for (int j = 0; j < NCLASS; j++) m = fmaxf(m, lg[lr][j]);
        float s = 0.f;
        for (int j = 0; j < NCLASS; j++) s += expf(lg[lr][j] - m);
        red[lr][0] = m;
        red[lr][1] = logf(s);
    }
    __syncthreads();

    if (lr < ROWS) {
        int gr = rowBase + lr;
        if (gr < M)
            out[(long)gr * NCLASS + c] = lg[lr][c] - red[lr][0] - red[lr][1];
    }
}

// ---------------------------------------------------------------------------
// Launch pipeline
// ---------------------------------------------------------------------------
extern "C" void kernel_launch(void* const* d_in, const int* in_sizes, int n_in,
                              void* d_out, int out_size) {
    const float* x   = (const float*)d_in[0];
    const int*   er  = (const int*)  d_in[1];
    const int*   ec  = (const int*)  d_in[2];
    const float* ev  = (const float*)d_in[3];
    const float* W1  = (const float*)d_in[4];
    const float* b1  = (const float*)d_in[5];
    const float* W2  = (const float*)d_in[6];
    const float* b2  = (const float*)d_in[7];
    const float* Wfc = (const float*)d_in[8];
    const float* bfc = (const float*)d_in[9];
    float* out = (float*)d_out;

    const int E = in_sizes[1];
    const int M = NNODES;

    float* buf1; float* buf2;
    cudaGetSymbolAddress((void**)&buf1, g_buf1);
    cudaGetSymbolAddress((void**)&buf2, g_buf2);

    // 1. CSR row pointers from sorted edge_rows
    rowptr_kernel<<<(NNODES + 1 + 255) / 256, 256>>>(er, E);

    // 2. support1 = x @ W1 + b1          [50000, 256]
    {
        dim3 grid(NHID / 128, (M + 127) / 128);
        sgemm_bias_kernel<NFEAT><<<grid, 256>>>(x, W1, b1, buf1, M);
    }

    // 3. h1 = relu(spmm(support1))
    spmm_relu_kernel<<<(M + 7) / 8, 256>>>(ec, ev, buf1, buf2);

    // 4. support2 = h1 @ W2 + b2
    {
        dim3 grid(NHID / 128, (M + 127) / 128);
        sgemm_bias_kernel<NHID><<<grid, 256>>>(buf2, W2, b2, buf1, M);
    }

    // 5. z = relu(spmm(support2))
    spmm_relu_kernel<<<(M + 7) / 8, 256>>>(ec, ev, buf1, buf2);

    // 6. out = log_softmax(z @ Wfc + bfc)
    fc_logsoftmax_kernel<<<(M + 5) / 6, 256>>>(buf2, Wfc, bfc, out, M);
}

// round 16
// speedup vs baseline: 1.1394x; 1.1394x over previous
#include <cuda_runtime.h>
#include <math.h>

#define NNODES 50000
#define NFEAT  512
#define NHID   256
#define NCLASS 40

// Scratch (no cudaMalloc allowed): ping-pong activation buffers + CSR row ptr.
__device__ float g_buf1[NNODES * NHID];
__device__ float g_buf2[NNODES * NHID];
__device__ int   g_rowptr[NNODES + 1];

// ---------------------------------------------------------------------------
// Build CSR row pointers from sorted edge_rows via per-row lower_bound.
// ---------------------------------------------------------------------------
__global__ void rowptr_kernel(const int* __restrict__ rows, int E) {
    int r = blockIdx.x * blockDim.x + threadIdx.x;
    if (r > NNODES) return;
    int lo = 0, hi = E;
    while (lo < hi) {
        int mid = (lo + hi) >> 1;
        if (rows[mid] < r) lo = mid + 1; else hi = mid;
    }
    g_rowptr[r] = lo;
}

// ---------------------------------------------------------------------------
// SGEMM + bias: C[M, 256] = A[M, K] @ B[K, 256] + bias
// 128x128 tile, BK=8, 256 threads, 8x8 microtile in SPLIT-TILE layout
// (conflict-free smem). Plain FFMA (FFMA2 measured half-rate -> neutral).
// Register double-buffer of the smem operand fragments — k+1's LDS
// issues before k's FMA block so LDS latency (29cyc) stays off the fma
// critical path (fma pipe idle was 43% at baseline).
// Double-buffered smem pipeline; unroll capped at 2; 2 CTAs/SM pinned.
// ---------------------------------------------------------------------------
template <int K>
__global__ __launch_bounds__(256, 2)
void sgemm_bias_kernel(const float* __restrict__ A,
                       const float* __restrict__ B,
                       const float* __restrict__ bias,
                       float* __restrict__ C, int M) {
    __shared__ float As[2][8][128];   // transposed A tile: As[s][k][m]
    __shared__ float Bs[2][8][128];   // Bs[s][k][n]

    const int tid = threadIdx.x;
    const int tx = tid % 16;
    const int ty = tid / 16;
    const int rowBase = blockIdx.y * 128;
    const int colBase = blockIdx.x * 128;

    const int aRow = tid >> 1;
    const int aK4  = (tid & 1) * 4;
    const int bRow = tid >> 5;
    const int bC4  = (tid & 31) * 4;

    float acc[8][8];
#pragma unroll
    for (int i = 0; i < 8; i++)
#pragma unroll
        for (int j = 0; j < 8; j++) acc[i][j] = 0.f;

    const int gARow = rowBase + aRow;
    const bool aValid = (gARow < M);

    // ---- prologue: load k-slice 0 into stage 0 ----
    {
        float4 av = make_float4(0.f, 0.f, 0.f, 0.f);
        if (aValid)
            av = *reinterpret_cast<const float4*>(&A[(long)gARow * K + aK4]);
        As[0][aK4 + 0][aRow] = av.x;
        As[0][aK4 + 1][aRow] = av.y;
        As[0][aK4 + 2][aRow] = av.z;
        As[0][aK4 + 3][aRow] = av.w;
        float4 bv = *reinterpret_cast<const float4*>(&B[(long)bRow * NHID + colBase + bC4]);
        *reinterpret_cast<float4*>(&Bs[0][bRow][bC4]) = bv;
    }
    __syncthreads();

#pragma unroll 2
    for (int kb = 0; kb < K; kb += 8) {
        const int cur = (kb >> 3) & 1;
        const bool hasNext = (kb + 8 < K);

        // prefetch next k-slice from gmem into registers
        float4 av = make_float4(0.f, 0.f, 0.f, 0.f);
        float4 bv = make_float4(0.f, 0.f, 0.f, 0.f);
        if (hasNext) {
            if (aValid)
                av = *reinterpret_cast<const float4*>(&A[(long)gARow * K + kb + 8 + aK4]);
            bv = *reinterpret_cast<const float4*>(&B[(long)(kb + 8 + bRow) * NHID + colBase + bC4]);
        }

        // compute on current stage with REGISTER DOUBLE-BUFFERED operands:
        // k+1's LDS issues before k's FMA block.
        float a[2][8], b[2][8];
        *reinterpret_cast<float4*>(&a[0][0]) = *reinterpret_cast<const float4*>(&As[cur][0][ty * 4]);
        *reinterpret_cast<float4*>(&a[0][4]) = *reinterpret_cast<const float4*>(&As[cur][0][64 + ty * 4]);
        *reinterpret_cast<float4*>(&b[0][0]) = *reinterpret_cast<const float4*>(&Bs[cur][0][tx * 4]);
        *reinterpret_cast<float4*>(&b[0][4]) = *reinterpret_cast<const float4*>(&Bs[cur][0][64 + tx * 4]);

#pragma unroll
        for (int k = 0; k < 8; k++) {
            const int pc = k & 1;        // operand set for this k (const-folds)
            const int pn = pc ^ 1;       // operand set being filled for k+1
            if (k < 7) {
                *reinterpret_cast<float4*>(&a[pn][0]) = *reinterpret_cast<const float4*>(&As[cur][k + 1][ty * 4]);
                *reinterpret_cast<float4*>(&a[pn][4]) = *reinterpret_cast<const float4*>(&As[cur][k + 1][64 + ty * 4]);
                *reinterpret_cast<float4*>(&b[pn][0]) = *reinterpret_cast<const float4*>(&Bs[cur][k + 1][tx * 4]);
                *reinterpret_cast<float4*>(&b[pn][4]) = *reinterpret_cast<const float4*>(&Bs[cur][k + 1][64 + tx * 4]);
            }
#pragma unroll
            for (int i = 0; i < 8; i++)
#pragma unroll
                for (int j = 0; j < 8; j++)
                    acc[i][j] = fmaf(a[pc][i], b[pc][j], acc[i][j]);
        }

        // store gmem-prefetched slice into the other smem stage
        if (hasNext) {
            const int nxt = cur ^ 1;
            As[nxt][aK4 + 0][aRow] = av.x;
            As[nxt][aK4 + 1][aRow] = av.y;
            As[nxt][aK4 + 2][aRow] = av.z;
            As[nxt][aK4 + 3][aRow] = av.w;
            *reinterpret_cast<float4*>(&Bs[nxt][bRow][bC4]) = bv;
            __syncthreads();
        }
    }

    // Epilogue: add bias, store both column halves (bounds-checked on M).
    float bcol[8];
#pragma unroll
    for (int j = 0; j < 4; j++) bcol[j] = bias[colBase + tx * 4 + j];
#pragma unroll
    for (int j = 4; j < 8; j++) bcol[j] = bias[colBase + 64 + tx * 4 + (j - 4)];

#pragma unroll
    for (int i = 0; i < 8; i++) {
        const int row = rowBase + (i < 4 ? ty * 4 + i : 64 + ty * 4 + (i - 4));
        if (row < M) {
            float4 v0 = make_float4(acc[i][0] + bcol[0], acc[i][1] + bcol[1],
                                    acc[i][2] + bcol[2], acc[i][3] + bcol[3]);
            float4 v1 = make_float4(acc[i][4] + bcol[4], acc[i][5] + bcol[5],
                                    acc[i][6] + bcol[6], acc[i][7] + bcol[7]);
            *reinterpret_cast<float4*>(&C[(long)row * NHID + colBase + tx * 4]) = v0;
            *reinterpret_cast<float4*>(&C[(long)row * NHID + colBase + 64 + tx * 4]) = v1;
        }
    }
}

// ---------------------------------------------------------------------------
// SpMM + ReLU (measured-good round-5 version): one block (64 threads) per
// row; each thread owns 4 features via float4. Edge (col,val) pairs staged
// through smem in chunks of 64.
// ---------------------------------------------------------------------------
__global__ __launch_bounds__(64)
void spmm_relu_kernel(const int* __restrict__ cols,
                      const float* __restrict__ vals,
                      const float* __restrict__ H,
                      float* __restrict__ out) {
    __shared__ int   sc[64];
    __shared__ float sv[64];

    const int r = blockIdx.x;
    const int f4 = threadIdx.x;            // float4 index: features [4*f4, 4*f4+3]
    const int start = g_rowptr[r];
    const int end   = g_rowptr[r + 1];

    float4 acc = make_float4(0.f, 0.f, 0.f, 0.f);
    for (int base = start; base < end; base += 64) {
        int n = min(64, end - base);
        if (f4 < n) {
            sc[f4] = cols[base + f4];
            sv[f4] = vals[base + f4];
        }
        __syncthreads();
#pragma unroll 4
        for (int i = 0; i < n; i++) {
            float v = sv[i];
            float4 h = *reinterpret_cast<const float4*>(&H[(long)sc[i] * NHID + f4 * 4]);
            acc.x = fmaf(v, h.x, acc.x);
            acc.y = fmaf(v, h.y, acc.y);
            acc.z = fmaf(v, h.z, acc.z);
            acc.w = fmaf(v, h.w, acc.w);
        }
        __syncthreads();
    }
    float4 res = make_float4(fmaxf(acc.x, 0.f), fmaxf(acc.y, 0.f),
                             fmaxf(acc.z, 0.f), fmaxf(acc.w, 0.f));
    *reinterpret_cast<float4*>(&out[(long)r * NHID + f4 * 4]) = res;
}

// ---------------------------------------------------------------------------
// Fused FC + log_softmax: out[r, c] = log_softmax(Z[r,:] @ Wfc + bfc)[c]
// 256 threads; 6 rows/block x 40 classes (threads 240..255 idle).
// ---------------------------------------------------------------------------
__global__ __launch_bounds__(256)
void fc_logsoftmax_kernel(const float* __restrict__ Z,
                          const float* __restrict__ Wfc,
                          const float* __restrict__ bfc,
                          float* __restrict__ out, int M) {
    const int ROWS = 6;
    __shared__ float zs[ROWS][NHID];
    __shared__ float lg[ROWS][NCLASS];
    __shared__ float red[ROWS][2];

    const int tid = threadIdx.x;
    const int rowBase = blockIdx.x * ROWS;

    for (int i = tid; i < ROWS * NHID; i += blockDim.x) {
        int lr = i / NHID, k = i % NHID;
        int gr = rowBase + lr;
        zs[lr][k] = (gr < M) ? Z[(long)gr * NHID + k] : 0.f;
    }
    __syncthreads();

    const int lr = tid / NCLASS;
    const int c  = tid % NCLASS;

    if (lr < ROWS) {
        float acc = bfc[c];
#pragma unroll 4
        for (int k = 0; k < NHID; k++)
            acc = fmaf(zs[lr][k], Wfc[k * NCLASS + c], acc);
        lg[lr][c] = acc;
    }
    __syncthreads();

    if (lr < ROWS && c == 0) {
        float m = -INFINITY;
        for (int j = 0; j < NCLASS; j++) m = fmaxf(m, lg[lr][j]);
        float s = 0.f;
        for (int j = 0; j < NCLASS; j++) s += expf(lg[lr][j] - m);
        red[lr][0] = m;
        red[lr][1] = logf(s);
    }
    __syncthreads();

    if (lr < ROWS) {
        int gr = rowBase + lr;
        if (gr < M)
            out[(long)gr * NCLASS + c] = lg[lr][c] - red[lr][0] - red[lr][1];
    }
}

// ---------------------------------------------------------------------------
// Launch pipeline
// ---------------------------------------------------------------------------
extern "C" void kernel_launch(void* const* d_in, const int* in_sizes, int n_in,
                              void* d_out, int out_size) {
    const float* x   = (const float*)d_in[0];
    const int*   er  = (const int*)  d_in[1];
    const int*   ec  = (const int*)  d_in[2];
    const float* ev  = (const float*)d_in[3];
    const float* W1  = (const float*)d_in[4];
    const float* b1  = (const float*)d_in[5];
    const float* W2  = (const float*)d_in[6];
    const float* b2  = (const float*)d_in[7];
    const float* Wfc = (const float*)d_in[8];
    const float* bfc = (const float*)d_in[9];
    float* out = (float*)d_out;

    const int E = in_sizes[1];
    const int M = NNODES;

    float* buf1; float* buf2;
    cudaGetSymbolAddress((void**)&buf1, g_buf1);
    cudaGetSymbolAddress((void**)&buf2, g_buf2);

    // 1. CSR row pointers from sorted edge_rows
    rowptr_kernel<<<(NNODES + 1 + 255) / 256, 256>>>(er, E);

    // 2. support1 = x @ W1 + b1          [50000, 256]
    {
        dim3 grid(NHID / 128, (M + 127) / 128);
        sgemm_bias_kernel<NFEAT><<<grid, 256>>>(x, W1, b1, buf1, M);
    }

    // 3. h1 = relu(spmm(support1))
    spmm_relu_kernel<<<M, 64>>>(ec, ev, buf1, buf2);

    // 4. support2 = h1 @ W2 + b2
    {
        dim3 grid(NHID / 128, (M + 127) / 128);
        sgemm_bias_kernel<NHID><<<grid, 256>>>(buf2, W2, b2, buf1, M);
    }

    // 5. z = relu(spmm(support2))
    spmm_relu_kernel<<<M, 64>>>(ec, ev, buf1, buf2);

    // 6. out = log_softmax(z @ Wfc + bfc)
    fc_logsoftmax_kernel<<<(M + 5) / 6, 256>>>(buf2, Wfc, bfc, out, M);
}